// round 17
// baseline (speedup 1.0000x reference)
#include <cuda_runtime.h>
#include <cuda_bf16.h>
#include <math.h>
#include <stdint.h>

// Problem dims (fixed)
#define Bb 64
#define Tt 512
#define IN_DIM 512
#define Hh 1024
#define G4 4096
#define NCLS 1000
#define NBLK 128   // persistent grid; single wave on 148 SMs

// Scratch (device globals; no allocation allowed)
__device__ float  g_xg[(size_t)Bb * Tt * G4];    // layer-0 pre-activations
// h in bf16 B-fragment layout: uint2 per (kg, nt, lane)
__device__ uint2  g_hf0A[64 * 8 * 32];    // layer-0 h_hi ping
__device__ uint2  g_hf0B[64 * 8 * 32];    // layer-0 h_hi pong
__device__ uint2  g_hf0loA[64 * 8 * 32];  // layer-0 h_lo ping
__device__ uint2  g_hf0loB[64 * 8 * 32];  // layer-0 h_lo pong
__device__ uint2  g_hf1A[64 * 8 * 32];    // layer-1 h ping
__device__ uint2  g_hf1B[64 * 8 * 32];    // layer-1 h pong
// W_hh1 bf16 A-fragments, block-private: [bid][kg*2+mt][lane]
__device__ uint4  g_Wf1hh[NBLK * 64 * 2 * 32];   // 8 MB, L2-resident
__device__ float  g_hlast[Bb * Hh];

__device__ unsigned g_bar_count = 0;
__device__ unsigned g_bar_epoch = 0;

// ---------------------------------------------------------------------------
__global__ void zero6_kernel(float* a, float* b, float* c,
                             float* d, float* e, float* f, int n) {
    int i = blockIdx.x * blockDim.x + threadIdx.x;
    if (i < n) { a[i] = 0.f; b[i] = 0.f; c[i] = 0.f;
                 d[i] = 0.f; e[i] = 0.f; f[i] = 0.f; }
}

// ---------------------------------------------------------------------------
// helpers
// ---------------------------------------------------------------------------
__device__ __forceinline__ uint32_t f2tf32u(float x) {
    uint32_t u;
    asm("cvt.rna.tf32.f32 %0, %1;" : "=r"(u) : "f"(x));
    return u;
}

// low element = first arg
__device__ __forceinline__ uint32_t pack_bf16x2(float lo, float hi) {
    uint32_t r;
    asm("cvt.rn.bf16x2.f32 %0, %1, %2;" : "=r"(r) : "f"(hi), "f"(lo));
    return r;
}

// split a,b (fp32) into bf16 hi pair + bf16 lo pair (a in low half)
__device__ __forceinline__ void split_bf16x2(float a, float b,
                                             uint32_t& hi, uint32_t& lo) {
    __nv_bfloat16 ah = __float2bfloat16_rn(a);
    __nv_bfloat16 bh = __float2bfloat16_rn(b);
    float alo = a - __bfloat162float(ah);
    float blo = b - __bfloat162float(bh);
    hi = ((uint32_t)__bfloat16_as_ushort(bh) << 16) | (uint32_t)__bfloat16_as_ushort(ah);
    lo = pack_bf16x2(alo, blo);
}

__device__ __forceinline__ void mma_tf32(float c[4],
                                         uint32_t a0, uint32_t a1, uint32_t a2, uint32_t a3,
                                         uint32_t b0, uint32_t b1) {
    asm volatile(
        "mma.sync.aligned.m16n8k8.row.col.f32.tf32.tf32.f32 "
        "{%0,%1,%2,%3}, {%4,%5,%6,%7}, {%8,%9}, {%0,%1,%2,%3};"
        : "+f"(c[0]), "+f"(c[1]), "+f"(c[2]), "+f"(c[3])
        : "r"(a0), "r"(a1), "r"(a2), "r"(a3), "r"(b0), "r"(b1));
}

__device__ __forceinline__ void mma_bf16(float c[4],
                                         uint32_t a0, uint32_t a1, uint32_t a2, uint32_t a3,
                                         uint32_t b0, uint32_t b1) {
    asm volatile(
        "mma.sync.aligned.m16n8k16.row.col.f32.bf16.bf16.f32 "
        "{%0,%1,%2,%3}, {%4,%5,%6,%7}, {%8,%9}, {%0,%1,%2,%3};"
        : "+f"(c[0]), "+f"(c[1]), "+f"(c[2]), "+f"(c[3])
        : "r"(a0), "r"(a1), "r"(a2), "r"(a3), "r"(b0), "r"(b1));
}

__device__ __forceinline__ uint32_t smem_u32(const void* p) {
    uint32_t a;
    asm("{ .reg .u64 t; cvta.to.shared.u64 t, %1; cvt.u32.u64 %0, t; }"
        : "=r"(a) : "l"(p));
    return a;
}

__device__ __forceinline__ void cp16(uint32_t dst, const void* src) {
    asm volatile("cp.async.cg.shared.global [%0], [%1], 16;" :: "r"(dst), "l"(src));
}

// ---------------------------------------------------------------------------
// tf32 GEMM (proven): C = A @ W^T + bias1 + bias2, cp.async double-buffered.
// ---------------------------------------------------------------------------
__global__ __launch_bounds__(256, 2)
void tf32_gemm_async_kernel(const float* __restrict__ A,
                            const float* __restrict__ W,
                            const float* __restrict__ bias1,
                            const float* __restrict__ bias2,
                            float* __restrict__ C,
                            int M, int N, int K) {
    extern __shared__ float gsm[];
    float* Abuf[2] = { gsm,            gsm + 9216  };
    float* Wbuf[2] = { gsm + 4608,     gsm + 13824 };

    const int tid  = threadIdx.x;
    const int lane = tid & 31;
    const int warp = tid >> 5;
    const int wm = warp >> 2;
    const int wn = warp & 3;
    const int g  = lane >> 2;
    const int tg = lane & 3;

    const long m0 = (long)blockIdx.y * 128;
    const long n0 = (long)blockIdx.x * 128;
    const int ntiles = K >> 5;

    float acc[4][4][4];
#pragma unroll
    for (int i = 0; i < 4; i++)
#pragma unroll
        for (int j = 0; j < 4; j++)
#pragma unroll
            for (int r = 0; r < 4; r++) acc[i][j][r] = 0.f;

    auto stage = [&](int tile, int buf) {
        const long k0 = (long)tile * 32;
        uint32_t sa = smem_u32(Abuf[buf]);
        uint32_t sw = smem_u32(Wbuf[buf]);
#pragma unroll
        for (int i = 0; i < 4; i++) {
            int idx = tid + i * 256;
            int r = idx >> 3;
            int c4 = (idx & 7) * 4;
            uint32_t off = (uint32_t)(r * 36 + c4) * 4u;
            cp16(sa + off, &A[(m0 + r) * K + k0 + c4]);
            cp16(sw + off, &W[(n0 + r) * K + k0 + c4]);
        }
        asm volatile("cp.async.commit_group;");
    };

    stage(0, 0);
    stage(1, 1);

    for (int t = 0; t < ntiles; t++) {
        const int buf = t & 1;
        asm volatile("cp.async.wait_group 1;");
        __syncthreads();

        const float* As = Abuf[buf];
        const float* Ws = Wbuf[buf];
#pragma unroll
        for (int k8 = 0; k8 < 4; k8++) {
            const int kb = k8 * 8;
            uint32_t af[4][4];
#pragma unroll
            for (int mt = 0; mt < 4; mt++) {
                const float* ab = &As[(wm * 64 + mt * 16 + g) * 36 + kb + tg];
                af[mt][0] = f2tf32u(ab[0]);
                af[mt][2] = f2tf32u(ab[4]);
                af[mt][1] = f2tf32u(ab[8 * 36]);
                af[mt][3] = f2tf32u(ab[8 * 36 + 4]);
            }
            uint32_t bf[4][2];
#pragma unroll
            for (int nt = 0; nt < 4; nt++) {
                const float* bb = &Ws[(wn * 32 + nt * 8 + g) * 36 + kb + tg];
                bf[nt][0] = f2tf32u(bb[0]);
                bf[nt][1] = f2tf32u(bb[4]);
            }
#pragma unroll
            for (int mt = 0; mt < 4; mt++)
#pragma unroll
                for (int nt = 0; nt < 4; nt++)
                    mma_tf32(acc[mt][nt], af[mt][0], af[mt][1], af[mt][2], af[mt][3],
                             bf[nt][0], bf[nt][1]);
        }
        __syncthreads();
        if (t + 2 < ntiles) stage(t + 2, buf);
    }

#pragma unroll
    for (int mt = 0; mt < 4; mt++) {
#pragma unroll
        for (int nt = 0; nt < 4; nt++) {
            long row0 = m0 + wm * 64 + mt * 16 + g;
            long col  = n0 + wn * 32 + nt * 8 + tg * 2;
            float bsum0 = (bias1 ? bias1[col]     : 0.f) + (bias2 ? bias2[col]     : 0.f);
            float bsum1 = (bias1 ? bias1[col + 1] : 0.f) + (bias2 ? bias2[col + 1] : 0.f);
            float2 v0 = make_float2(acc[mt][nt][0] + bsum0, acc[mt][nt][1] + bsum1);
            float2 v1 = make_float2(acc[mt][nt][2] + bsum0, acc[mt][nt][3] + bsum1);
            *(float2*)&C[row0 * N + col] = v0;
            *(float2*)&C[(row0 + 8) * N + col] = v1;
        }
    }
}

// ---------------------------------------------------------------------------
// fp32 SGEMM (FC only)
// ---------------------------------------------------------------------------
__global__ void sgemm_bias_kernel(const float* __restrict__ A,
                                  const float* __restrict__ W,
                                  const float* __restrict__ bias1,
                                  const float* __restrict__ bias2,
                                  float* __restrict__ C,
                                  int M, int N, int K) {
    __shared__ __align__(16) float As[16 * 132];
    __shared__ __align__(16) float Ws[16 * 68];
    const int m0 = blockIdx.y * 128;
    const int n0 = blockIdx.x * 64;
    const int tid = threadIdx.x;
    const int tx = tid & 15;
    const int ty = tid >> 4;
    float acc[8][4] = {};

    for (int k0 = 0; k0 < K; k0 += 16) {
#pragma unroll
        for (int i = 0; i < 8; i++) {
            int idx = tid + i * 256;
            int k = idx & 15;
            int r = idx >> 4;
            As[k * 132 + r] = (m0 + r < M) ? A[(long)(m0 + r) * K + k0 + k] : 0.f;
        }
#pragma unroll
        for (int i = 0; i < 4; i++) {
            int idx = tid + i * 256;
            int k = idx & 15;
            int r = idx >> 4;
            Ws[k * 68 + r] = (n0 + r < N) ? W[(long)(n0 + r) * K + k0 + k] : 0.f;
        }
        __syncthreads();
#pragma unroll
        for (int kk = 0; kk < 16; kk++) {
            float4 b = *(const float4*)&Ws[kk * 68 + tx * 4];
            float4 a0 = *(const float4*)&As[kk * 132 + ty * 8];
            float4 a1 = *(const float4*)&As[kk * 132 + ty * 8 + 4];
            acc[0][0] += a0.x * b.x; acc[0][1] += a0.x * b.y; acc[0][2] += a0.x * b.z; acc[0][3] += a0.x * b.w;
            acc[1][0] += a0.y * b.x; acc[1][1] += a0.y * b.y; acc[1][2] += a0.y * b.z; acc[1][3] += a0.y * b.w;
            acc[2][0] += a0.z * b.x; acc[2][1] += a0.z * b.y; acc[2][2] += a0.z * b.z; acc[2][3] += a0.z * b.w;
            acc[3][0] += a0.w * b.x; acc[3][1] += a0.w * b.y; acc[3][2] += a0.w * b.z; acc[3][3] += a0.w * b.w;
            acc[4][0] += a1.x * b.x; acc[4][1] += a1.x * b.y; acc[4][2] += a1.x * b.z; acc[4][3] += a1.x * b.w;
            acc[5][0] += a1.y * b.x; acc[5][1] += a1.y * b.y; acc[5][2] += a1.y * b.z; acc[5][3] += a1.y * b.w;
            acc[6][0] += a1.z * b.x; acc[6][1] += a1.z * b.y; acc[6][2] += a1.z * b.z; acc[6][3] += a1.z * b.w;
            acc[7][0] += a1.w * b.x; acc[7][1] += a1.w * b.y; acc[7][2] += a1.w * b.z; acc[7][3] += a1.w * b.w;
        }
        __syncthreads();
    }

#pragma unroll
    for (int i = 0; i < 8; i++) {
        int m = m0 + ty * 8 + i;
        if (m >= M) continue;
#pragma unroll
        for (int j = 0; j < 4; j++) {
            int n = n0 + tx * 4 + j;
            if (n >= N) continue;
            float bsum = (bias1 ? bias1[n] : 0.f) + (bias2 ? bias2[n] : 0.f);
            C[(long)m * N + n] = acc[i][j] + bsum;
        }
    }
}

// ---------------------------------------------------------------------------
// Fused 2-layer persistent LSTM (wavefront), v3:
// Same dataflow and arithmetic order as R16 (merged h0_hi stream).
// Latency hardening: pass-2/3 B queues deepened to 8, queues + pass-3 W
// prefetched early (right after L0 partial store), W prefetch 1 kgl ahead.
// smem (floats): WihHi 16384 | WihLo 16384 | Ps 17408 | Ds 2176 | Xs 2048 | bs1 32
// ---------------------------------------------------------------------------
#define SMF_WHI 0
#define SMF_WLO 16384
#define SMF_PS  32768
#define SMF_DS  (SMF_PS + 17408)
#define SMF_XS  (SMF_DS + 2176)
#define SMF_BS  (SMF_XS + 2048)
#define SMF_TOT (SMF_BS + 32)     // 54432 floats = 217,728 B

__global__ __launch_bounds__(256, 1)
void lstm_fused_kernel(const float* __restrict__ xg0,
                       const float* __restrict__ W_hh0,
                       const float* __restrict__ W_ih1,
                       const float* __restrict__ W_hh1,
                       const float* __restrict__ b_ih1,
                       const float* __restrict__ b_hh1,
                       uint2* hf0A, uint2* hf0B,
                       uint2* hf0loA, uint2* hf0loB,
                       uint2* hf1A, uint2* hf1B,
                       uint4* gWhh1,
                       float* __restrict__ hlast) {
    extern __shared__ float smem[];
    uint4* WfHi = (uint4*)(smem + SMF_WHI);
    uint4* WfLo = (uint4*)(smem + SMF_WLO);
    float* Ps  = smem + SMF_PS;
    float* Ds  = smem + SMF_DS;
    float* Xs  = smem + SMF_XS;
    float* bs1 = smem + SMF_BS;

    const int tid  = threadIdx.x;      // 256
    const int lane = tid & 31;
    const int w    = tid >> 5;         // warp 0..7
    const int g    = lane >> 2;
    const int tg   = lane & 3;
    const int bid  = blockIdx.x;
    const int j0   = bid * 8;
    const int bp   = lane;
    const int jl   = w;

    __shared__ unsigned s_e0;
    if (tid == 0) s_e0 = *(volatile unsigned*)&g_bar_epoch;
    __syncthreads();
    const unsigned e0 = s_e0;

    // ---- one-time: L0 W_hh0 fragments -> registers (proven layout) ----
    uint4 af0[8], af1[8];
#pragma unroll
    for (int kgl = 0; kgl < 8; kgl++) {
        int kg = w * 8 + kgl;
        int k0 = kg * 16 + 2 * tg;
        int kh = k0 + 8;
        int r;
        long rowA, rowB;
        r = g;       rowA = (long)((r >> 3) * Hh + j0 + (r & 7)) * Hh;
        r = g + 8;   rowB = (long)((r >> 3) * Hh + j0 + (r & 7)) * Hh;
        af0[kgl].x = pack_bf16x2(W_hh0[rowA + k0], W_hh0[rowA + k0 + 1]);
        af0[kgl].y = pack_bf16x2(W_hh0[rowB + k0], W_hh0[rowB + k0 + 1]);
        af0[kgl].z = pack_bf16x2(W_hh0[rowA + kh], W_hh0[rowA + kh + 1]);
        af0[kgl].w = pack_bf16x2(W_hh0[rowB + kh], W_hh0[rowB + kh + 1]);
        r = 16 + g;  rowA = (long)((r >> 3) * Hh + j0 + (r & 7)) * Hh;
        r = 24 + g;  rowB = (long)((r >> 3) * Hh + j0 + (r & 7)) * Hh;
        af1[kgl].x = pack_bf16x2(W_hh0[rowA + k0], W_hh0[rowA + k0 + 1]);
        af1[kgl].y = pack_bf16x2(W_hh0[rowB + k0], W_hh0[rowB + k0 + 1]);
        af1[kgl].z = pack_bf16x2(W_hh0[rowA + kh], W_hh0[rowA + kh + 1]);
        af1[kgl].w = pack_bf16x2(W_hh0[rowB + kh], W_hh0[rowB + kh + 1]);
    }

    // ---- one-time: W_ih1 split (hi/lo) fragments -> smem (K=1024) ----
    for (int i = tid; i < 4096; i += 256) {
        int l   = i & 31;
        int grp = i >> 5;             // kg*2 + mt
        int mt  = grp & 1;
        int kg  = grp >> 1;
        int gg = l >> 2, tt = l & 3;
        int kl = kg * 16 + 2 * tt;
        int kh = kl + 8;
        int rA = mt * 16 + gg;
        int rB = rA + 8;
        long rowA = (long)((rA >> 3) * Hh + j0 + (rA & 7)) * Hh;
        long rowB = (long)((rB >> 3) * Hh + j0 + (rB & 7)) * Hh;
        uint4 vh, vl;
        split_bf16x2(W_ih1[rowA + kl], W_ih1[rowA + kl + 1], vh.x, vl.x);
        split_bf16x2(W_ih1[rowB + kl], W_ih1[rowB + kl + 1], vh.y, vl.y);
        split_bf16x2(W_ih1[rowA + kh], W_ih1[rowA + kh + 1], vh.z, vl.z);
        split_bf16x2(W_ih1[rowB + kh], W_ih1[rowB + kh + 1], vh.w, vl.w);
        WfHi[i] = vh;
        WfLo[i] = vl;
    }

    // ---- one-time: W_hh1 bf16 fragments -> block-private GLOBAL ----
    uint4* myWhh = gWhh1 + (long)bid * 4096;
    for (int i = tid; i < 4096; i += 256) {
        int l   = i & 31;
        int grp = i >> 5;
        int mt  = grp & 1;
        int kg  = grp >> 1;
        int gg = l >> 2, tt = l & 3;
        int kl = kg * 16 + 2 * tt;
        int kh = kl + 8;
        int rA = mt * 16 + gg;
        int rB = rA + 8;
        long rowA = (long)((rA >> 3) * Hh + j0 + (rA & 7)) * Hh;
        long rowB = (long)((rB >> 3) * Hh + j0 + (rB & 7)) * Hh;
        uint4 v;
        v.x = pack_bf16x2(W_hh1[rowA + kl], W_hh1[rowA + kl + 1]);
        v.y = pack_bf16x2(W_hh1[rowB + kl], W_hh1[rowB + kl + 1]);
        v.z = pack_bf16x2(W_hh1[rowA + kh], W_hh1[rowA + kh + 1]);
        v.w = pack_bf16x2(W_hh1[rowB + kh], W_hh1[rowB + kh + 1]);
        myWhh[i] = v;
    }

    // ---- one-time: L1 bias sums ----
    if (tid < 32) {
        int gate = tid >> 3, jj = tid & 7;
        bs1[tid] = b_ih1[gate * Hh + j0 + jj] + b_hh1[gate * Hh + j0 + jj];
    }

    // producer frag-write geometry (proven)
    const int jj16 = ((bid & 1) << 3) + jl;
    const int tgp  = (jj16 & 7) >> 1;
    const int bsub = ((jj16 >= 8) ? 4 : 0) + (jj16 & 1) * 2;
    const int kgp  = bid >> 1;

    float cst0[2] = {0.f, 0.f};
    float cst1[2] = {0.f, 0.f};
    __syncthreads();   // also makes myWhh global writes visible block-wide

    // stage Xs for s=0
#pragma unroll
    for (int i = 0; i < 8; i++) {
        int idx = tid + i * 256;
        int jj = idx & 7;
        int gate = (idx >> 3) & 3;
        int b = idx >> 5;
        Xs[(gate * 8 + jj) * 64 + b] =
            xg0[((long)b * Tt + 0) * G4 + gate * Hh + j0 + jj];
    }

    for (int s = 0; s <= Tt; s++) {
        const uint2* hf0prev   = (s & 1) ? hf0A   : hf0B;
        uint2*       hf0out    = (s & 1) ? hf0B   : hf0A;
        const uint2* hf0loprev = (s & 1) ? hf0loA : hf0loB;
        uint2*       hf0loout  = (s & 1) ? hf0loB : hf0loA;
        const uint2* hf1prev   = (s & 1) ? hf1A   : hf1B;
        uint2*       hf1out    = (s & 1) ? hf1B   : hf1A;

        // ---- MERGED loop: B = h0_hi; feeds L0 (af) and L1-ih (WfHi+WfLo) ----
        float aL0[8][4], aL1[8][4];   // L0 accs (rows 0..15 / 16..31)
        float aM0[8][4], aM1[8][4];   // L1 accs
#pragma unroll
        for (int nt = 0; nt < 8; nt++)
#pragma unroll
            for (int r = 0; r < 4; r++) {
                aL0[nt][r] = 0.f; aL1[nt][r] = 0.f;
                aM0[nt][r] = 0.f; aM1[nt][r] = 0.f;
            }
        {
            const uint2* hb = hf0prev + (w * 64) * 32 + lane;
            uint2 Bq[4];
#pragma unroll
            for (int p = 0; p < 4; p++) Bq[p] = __ldcg(hb + p * 32);
#pragma unroll
            for (int kgl = 0; kgl < 8; kgl++) {
                uint4 wh0 = WfHi[((w * 8 + kgl) * 2 + 0) * 32 + lane];
                uint4 wh1 = WfHi[((w * 8 + kgl) * 2 + 1) * 32 + lane];
                uint4 wl0 = WfLo[((w * 8 + kgl) * 2 + 0) * 32 + lane];
                uint4 wl1 = WfLo[((w * 8 + kgl) * 2 + 1) * 32 + lane];
#pragma unroll
                for (int nt = 0; nt < 8; nt++) {
                    int i = kgl * 8 + nt;
                    uint2 B = Bq[i & 3];
                    if (i + 4 < 64) Bq[i & 3] = __ldcg(hb + (i + 4) * 32);
                    mma_bf16(aL0[nt], af0[kgl].x, af0[kgl].y, af0[kgl].z, af0[kgl].w, B.x, B.y);
                    mma_bf16(aL1[nt], af1[kgl].x, af1[kgl].y, af1[kgl].z, af1[kgl].w, B.x, B.y);
                    mma_bf16(aM0[nt], wh0.x, wh0.y, wh0.z, wh0.w, B.x, B.y);
                    mma_bf16(aM1[nt], wh1.x, wh1.y, wh1.z, wh1.w, B.x, B.y);
                    mma_bf16(aM0[nt], wl0.x, wl0.y, wl0.z, wl0.w, B.x, B.y);
                    mma_bf16(aM1[nt], wl1.x, wl1.y, wl1.z, wl1.w, B.x, B.y);
                }
            }
        }

        // ---- store L0 partials (frees aL regs) ----
        {
            float* myPs = Ps + w * 2176;
#pragma unroll
            for (int nt = 0; nt < 8; nt++) {
                int c0 = nt * 8 + tg * 2;
                *(float2*)&myPs[g * 68 + c0]        = make_float2(aL0[nt][0], aL0[nt][1]);
                *(float2*)&myPs[(g + 8) * 68 + c0]  = make_float2(aL0[nt][2], aL0[nt][3]);
                *(float2*)&myPs[(16 + g) * 68 + c0] = make_float2(aL1[nt][0], aL1[nt][1]);
                *(float2*)&myPs[(24 + g) * 68 + c0] = make_float2(aL1[nt][2], aL1[nt][3]);
            }
        }

        // ---- early prefetch for passes 2 & 3 (aL regs are dead now) ----
        const uint2* hb2 = hf0loprev + (w * 64) * 32 + lane;
        const uint2* hb3 = hf1prev   + (w * 64) * 32 + lane;
        uint2 Bq2[8], Bq3[8];
#pragma unroll
        for (int p = 0; p < 8; p++) Bq2[p] = __ldcg(hb2 + p * 32);
#pragma unroll
        for (int p = 0; p < 8; p++) Bq3[p] = __ldcg(hb3 + p * 32);
        uint4 w3a = __ldcg(myWhh + ((w * 8) * 2 + 0) * 32 + lane);
        uint4 w3b = __ldcg(myWhh + ((w * 8) * 2 + 1) * 32 + lane);

        // ---- Pass 2: B = h0_lo; W = WfHi (depth-8 queue) ----
        {
#pragma unroll
            for (int kgl = 0; kgl < 8; kgl++) {
                uint4 wh0 = WfHi[((w * 8 + kgl) * 2 + 0) * 32 + lane];
                uint4 wh1 = WfHi[((w * 8 + kgl) * 2 + 1) * 32 + lane];
#pragma unroll
                for (int nt = 0; nt < 8; nt++) {
                    int i = kgl * 8 + nt;
                    uint2 B = Bq2[i & 7];
                    if (i + 8 < 64) Bq2[i & 7] = __ldcg(hb2 + (i + 8) * 32);
                    mma_bf16(aM0[nt], wh0.x, wh0.y, wh0.z, wh0.w, B.x, B.y);
                    mma_bf16(aM1[nt], wh1.x, wh1.y, wh1.z, wh1.w, B.x, B.y);
                }
            }
        }
        // ---- Pass 3: B = h1_prev; W = gWhh1 (depth-8 queue + W prefetch) ----
        {
#pragma unroll
            for (int kgl = 0; kgl < 8; kgl++) {
                uint4 wh0 = w3a;
                uint4 wh1 = w3b;
                if (kgl < 7) {
                    w3a = __ldcg(myWhh + ((w * 8 + kgl + 1) * 2 + 0) * 32 + lane);
                    w3b = __ldcg(myWhh + ((w * 8 + kgl + 1) * 2 + 1) * 32 + lane);
                }
#pragma unroll
                for (int nt = 0; nt < 8; nt++) {
                    int i = kgl * 8 + nt;
                    uint2 B = Bq3[i & 7];
                    if (i + 8 < 64) Bq3[i & 7] = __ldcg(hb3 + (i + 8) * 32);
                    mma_bf16(aM0[nt], wh0.x, wh0.y, wh0.z, wh0.w, B.x, B.y);
                    mma_bf16(aM1[nt], wh1.x, wh1.y, wh1.z, wh1.w, B.x, B.y);
                }
            }
        }
        __syncthreads();   // Ps(L0) complete

        // ---- reduce L0 partials -> Ds ----
        {
            int row  = tid >> 3;
            int col0 = (tid & 7) * 8;
            float4 s0 = make_float4(0.f, 0.f, 0.f, 0.f);
            float4 s1 = make_float4(0.f, 0.f, 0.f, 0.f);
#pragma unroll
            for (int ww = 0; ww < 8; ww++) {
                const float* p = Ps + ww * 2176 + row * 68 + col0;
                float4 a = *(const float4*)p;
                float4 b = *(const float4*)(p + 4);
                s0.x += a.x; s0.y += a.y; s0.z += a.z; s0.w += a.w;
                s1.x += b.x; s1.y += b.y; s1.z += b.z; s1.w += b.w;
            }
            *(float4*)&Ds[row * 68 + col0]     = s0;
            *(float4*)&Ds[row * 68 + col0 + 4] = s1;
        }
        __syncthreads();

        // ---- L0 pointwise + h0 frag writes; also store L1 partials to Ps ----
        if (s < Tt) {
#pragma unroll
            for (int bl = 0; bl < 2; bl++) {
                int b = bp * 2 + bl;
                float pi = Ds[jl * 68 + b]        + Xs[jl * 64 + b];
                float pf = Ds[(8 + jl) * 68 + b]  + Xs[(8 + jl) * 64 + b];
                float pg = Ds[(16 + jl) * 68 + b] + Xs[(16 + jl) * 64 + b];
                float po = Ds[(24 + jl) * 68 + b] + Xs[(24 + jl) * 64 + b];
                float gi = 1.f / (1.f + expf(-pi));
                float gf = 1.f / (1.f + expf(-pf));
                float gg2 = tanhf(pg);
                float go = 1.f / (1.f + expf(-po));
                float c = gf * cst0[bl] + gi * gg2;
                cst0[bl] = c;
                float h = go * tanhf(c);
                long fo = (kgp * 8 + (b >> 3)) * 32 + (b & 7) * 4 + tgp;
                __nv_bfloat16 hhi = __float2bfloat16_rn(h);
                float hlo = h - __bfloat162float(hhi);
                *(__nv_bfloat16*)((char*)(hf0out + fo) + bsub)   = hhi;
                *(__nv_bfloat16*)((char*)(hf0loout + fo) + bsub) = __float2bfloat16_rn(hlo);
            }
        }
        {   // L1 partials (Ps safe to overwrite: all threads passed the reduce)
            float* myPs = Ps + w * 2176;
#pragma unroll
            for (int nt = 0; nt < 8; nt++) {
                int c0 = nt * 8 + tg * 2;
                *(float2*)&myPs[g * 68 + c0]        = make_float2(aM0[nt][0], aM0[nt][1]);
                *(float2*)&myPs[(g + 8) * 68 + c0]  = make_float2(aM0[nt][2], aM0[nt][3]);
                *(float2*)&myPs[(16 + g) * 68 + c0] = make_float2(aM1[nt][0], aM1[nt][1]);
                *(float2*)&myPs[(24 + g) * 68 + c0] = make_float2(aM1[nt][2], aM1[nt][3]);
            }
        }
        __syncthreads();

        // ---- reduce L1 partials -> Ds ----
        {
            int row  = tid >> 3;
            int col0 = (tid & 7) * 8;
            float4 s0 = make_float4(0.f, 0.f, 0.f, 0.f);
            float4 s1 = make_float4(0.f, 0.f, 0.f, 0.f);
#pragma unroll
            for (int ww = 0; ww < 8; ww++) {
                const float* p = Ps + ww * 2176 + row * 68 + col0;
                float4 a = *(const float4*)p;
                float4 b = *(const float4*)(p + 4);
                s0.x += a.x; s0.y += a.y; s0.z += a.z; s0.w += a.w;
                s1.x += b.x; s1.y += b.y; s1.z += b.z; s1.w += b.w;
            }
            *(float4*)&Ds[row * 68 + col0]     = s0;
            *(float4*)&Ds[row * 68 + col0 + 4] = s1;
        }
        __syncthreads();

        // ---- L1 pointwise + h1 frag writes ----
        if (s >= 1) {
#pragma unroll
            for (int bl = 0; bl < 2; bl++) {
                int b = bp * 2 + bl;
                float pi = Ds[jl * 68 + b]        + bs1[jl];
                float pf = Ds[(8 + jl) * 68 + b]  + bs1[8 + jl];
                float pg = Ds[(16 + jl) * 68 + b] + bs1[16 + jl];
                float po = Ds[(24 + jl) * 68 + b] + bs1[24 + jl];
                float gi = 1.f / (1.f + expf(-pi));
                float gf = 1.f / (1.f + expf(-pf));
                float gg2 = tanhf(pg);
                float go = 1.f / (1.f + expf(-po));
                float c = gf * cst1[bl] + gi * gg2;
                cst1[bl] = c;
                float h = go * tanhf(c);
                char* fp = (char*)(hf1out + ((kgp * 8 + (b >> 3)) * 32 + (b & 7) * 4 + tgp)) + bsub;
                *(__nv_bfloat16*)fp = __float2bfloat16_rn(h);
                if (s == Tt) hlast[(long)b * Hh + j0 + jl] = h;
            }
        }

        __threadfence();
        __syncthreads();

        // ---- arrive ----
        if (tid == 0) {
            unsigned arrived = atomicAdd(&g_bar_count, 1u);
            if (arrived == NBLK - 1) {
                *(volatile unsigned*)&g_bar_count = 0u;
                __threadfence();
                *(volatile unsigned*)&g_bar_epoch = e0 + (unsigned)s + 1u;
            }
        }

        // ---- overlapped tail: stage next Xs ----
        if (s + 1 < Tt) {
#pragma unroll
            for (int i = 0; i < 8; i++) {
                int idx = tid + i * 256;
                int jj = idx & 7;
                int gate = (idx >> 3) & 3;
                int b = idx >> 5;
                Xs[(gate * 8 + jj) * 64 + b] =
                    xg0[((long)b * Tt + (s + 1)) * G4 + gate * Hh + j0 + jj];
            }
        }

        // ---- wait ----
        if (tid == 0) {
            while (*(volatile unsigned*)&g_bar_epoch < e0 + (unsigned)s + 1u) { }
        }
        __syncthreads();
    }
}

// ---------------------------------------------------------------------------
// kernel_launch: 4 graph nodes
// ---------------------------------------------------------------------------
extern "C" void kernel_launch(void* const* d_in, const int* in_sizes, int n_in,
                              void* d_out, int out_size) {
    const float* x     = (const float*)d_in[0];
    const float* W_ih0 = (const float*)d_in[1];
    const float* W_hh0 = (const float*)d_in[2];
    const float* b_ih0 = (const float*)d_in[3];
    const float* b_hh0 = (const float*)d_in[4];
    const float* W_ih1 = (const float*)d_in[5];
    const float* W_hh1 = (const float*)d_in[6];
    const float* b_ih1 = (const float*)d_in[7];
    const float* b_hh1 = (const float*)d_in[8];
    const float* fc_w  = (const float*)d_in[9];
    const float* fc_b  = (const float*)d_in[10];
    float* out = (float*)d_out;

    float *xg, *hlast;
    uint2 *hf0A, *hf0B, *hf0loA, *hf0loB, *hf1A, *hf1B;
    uint4 *gWhh1;
    cudaGetSymbolAddress((void**)&xg, g_xg);
    cudaGetSymbolAddress((void**)&hf0A, g_hf0A);
    cudaGetSymbolAddress((void**)&hf0B, g_hf0B);
    cudaGetSymbolAddress((void**)&hf0loA, g_hf0loA);
    cudaGetSymbolAddress((void**)&hf0loB, g_hf0loB);
    cudaGetSymbolAddress((void**)&hf1A, g_hf1A);
    cudaGetSymbolAddress((void**)&hf1B, g_hf1B);
    cudaGetSymbolAddress((void**)&gWhh1, g_Wf1hh);
    cudaGetSymbolAddress((void**)&hlast, g_hlast);

    const int fragN = 64 * 8 * 32 * 2;                  // uint32 per frag buffer
    const int SMEM_FUSED = SMF_TOT * sizeof(float);     // 217,728 B
    const int SMEM_GEMM  = 4 * 4608 * sizeof(float);    // 73,728 B

    static int smem_set = 0;
    if (!smem_set) {
        cudaFuncSetAttribute(lstm_fused_kernel,
                             cudaFuncAttributeMaxDynamicSharedMemorySize,
                             SMEM_FUSED);
        cudaFuncSetAttribute(tf32_gemm_async_kernel,
                             cudaFuncAttributeMaxDynamicSharedMemorySize,
                             SMEM_GEMM);
        smem_set = 1;
    }

    // zero the six h frag ring buffers
    zero6_kernel<<<(fragN + 255) / 256, 256>>>((float*)hf0A, (float*)hf0B,
                                               (float*)hf0loA, (float*)hf0loB,
                                               (float*)hf1A, (float*)hf1B, fragN);

    // xg0 = x @ W_ih0^T + b_ih0 + b_hh0   (M=32768, N=4096, K=512)
    {
        dim3 grid(G4 / 128, (Bb * Tt) / 128);
        tf32_gemm_async_kernel<<<grid, 256, SMEM_GEMM>>>(x, W_ih0, b_ih0, b_hh0, xg,
                                                         Bb * Tt, G4, IN_DIM);
    }

    // fused 2-layer recurrence (513 wavefront iterations)
    lstm_fused_kernel<<<NBLK, 256, SMEM_FUSED>>>(
        xg, W_hh0, W_ih1, W_hh1, b_ih1, b_hh1,
        hf0A, hf0B, hf0loA, hf0loB, hf1A, hf1B, gWhh1, hlast);

    // FC: out[64,1000] = hlast @ fc_w^T + fc_b
    {
        dim3 grid((NCLS + 63) / 64, (Bb + 127) / 128);
        sgemm_bias_kernel<<<grid, 256>>>(hlast, fc_w, fc_b, nullptr, out,
                                         Bb, NCLS, Hh);
    }
}